// round 12
// baseline (speedup 1.0000x reference)
#include <cuda_runtime.h>
#include <cuda_bf16.h>

#define N_USERS 100000
#define N_ITEMS 50000
#define NN      150000
#define NE      2000000
#define DD      64
#define NB      16384
#define SB      586      // ceil(NN/256) scan blocks

// ---------------- scratch (device globals) ----------------------------------
__device__ float          g_x [NN*DD];    // layer outputs (fp32)
__device__ __nv_bfloat16  g_hb[NN*DD];    // h = x@W in bf16 (gather payload)
__device__ float g_as [NN*4];
__device__ float g_ad [NN*4];
__device__ int   g_adj[NE];
__device__ int   g_cnt[NN];
__device__ int   g_off[NN+1];
__device__ int   g_pos[NN];
__device__ int   g_spine[1024];
__device__ int   g_is64;

// ---------------- helpers ---------------------------------------------------
__device__ __forceinline__ float lrelu(float x) { return x > 0.f ? x : 0.2f * x; }
__device__ __forceinline__ float eluf (float v) { return v > 0.f ? v : expf(v) - 1.f; }
__device__ __forceinline__ float2 bf2f(unsigned u) {
    return __bfloat1622float2(*(__nv_bfloat162*)&u);
}

// ---------------- init: zero counters + dtype detect -------------------------
__global__ void k_init(const int* __restrict__ ei) {
    int i = blockIdx.x * blockDim.x + threadIdx.x;
    if (i < NN) g_cnt[i] = 0;
    if (blockIdx.x == 0 && threadIdx.x == 0) {
        int all0 = 1;
        for (int k = 0; k < 64; k++)
            if (ei[2 * k + 1] != 0) { all0 = 0; break; }
        g_is64 = all0;
    }
}

__global__ void k_count(const void* __restrict__ ei) {
    int e = blockIdx.x * blockDim.x + threadIdx.x;
    if (e >= NE) return;
    int d = g_is64 ? (int)((const long long*)ei)[NE + e]
                   : ((const int*)ei)[NE + e];
    atomicAdd(&g_cnt[d], 1);
}

// block sums -> spine (shuffle reduce)
__global__ void k_s1() {
    __shared__ int ws[8];
    int t = threadIdx.x;
    int i = blockIdx.x * 256 + t;
    int v = (i < NN) ? g_cnt[i] : 0;
#pragma unroll
    for (int d = 16; d; d >>= 1) v += __shfl_xor_sync(0xffffffffu, v, d);
    if ((t & 31) == 0) ws[t >> 5] = v;
    __syncthreads();
    if (t < 8) {
        int s = ws[t];
#pragma unroll
        for (int d = 4; d; d >>= 1) s += __shfl_xor_sync(0xffu, s, d);
        if (t == 0) g_spine[blockIdx.x] = s;
    }
}

// 1024-wide exclusive scan (shuffle-based)
template <int NVALID>
__device__ __forceinline__ void scan1024(int* arr) {
    __shared__ int ws[32];
    int t = threadIdx.x;
    int orig = (t < NVALID) ? arr[t] : 0;
    int v = orig;
#pragma unroll
    for (int d = 1; d < 32; d <<= 1) {
        int u = __shfl_up_sync(0xffffffffu, v, d);
        if ((t & 31) >= d) v += u;
    }
    if ((t & 31) == 31) ws[t >> 5] = v;
    __syncthreads();
    if (t < 32) {
        int s = ws[t];
#pragma unroll
        for (int d = 1; d < 32; d <<= 1) {
            int u = __shfl_up_sync(0xffffffffu, s, d);
            if (t >= d) s += u;
        }
        ws[t] = s;
    }
    __syncthreads();
    int incl = v + ((t >= 32) ? ws[(t >> 5) - 1] : 0);
    if (t < NVALID) arr[t] = incl - orig;
}

__global__ void k_s2() {
    scan1024<SB>(g_spine);
    if (threadIdx.x == 0) g_off[NN] = NE;
}

// per-block exclusive scan + spine offset (shuffle-based)
__global__ void k_s3() {
    __shared__ int ws[8];
    int t = threadIdx.x;
    int i = blockIdx.x * 256 + t;
    int orig = (i < NN) ? g_cnt[i] : 0;
    int v = orig;
#pragma unroll
    for (int d = 1; d < 32; d <<= 1) {
        int u = __shfl_up_sync(0xffffffffu, v, d);
        if ((t & 31) >= d) v += u;
    }
    if ((t & 31) == 31) ws[t >> 5] = v;
    __syncthreads();
    if (t < 8) {
        int s = ws[t];
#pragma unroll
        for (int d = 1; d < 8; d <<= 1) {
            int u = __shfl_up_sync(0xffu, s, d);
            if (t >= d) s += u;
        }
        ws[t] = s;
    }
    __syncthreads();
    int incl = v + ((t >= 32) ? ws[(t >> 5) - 1] : 0);
    int excl = incl - orig + g_spine[blockIdx.x];
    if (i < NN) { g_off[i] = excl; g_pos[i] = excl; }
}

__global__ void k_scatter(const void* __restrict__ ei) {
    int e = blockIdx.x * blockDim.x + threadIdx.x;
    if (e >= NE) return;
    int s, d;
    if (g_is64) {
        const long long* p = (const long long*)ei;
        s = (int)p[e]; d = (int)p[NE + e];
    } else {
        const int* p = (const int*)ei;
        s = p[e]; d = p[NE + e];
    }
    int pos = atomicAdd(&g_pos[d], 1);
    g_adj[pos] = s;
}

// ---------------- fused GEMM + alpha ------------------------------------------
// 128 threads, 64 nodes/block; thread = 4 nodes x 8 cols.
template <bool FIRST, int H>
__global__ void k_gemm(const float* __restrict__ W,
                       const float* __restrict__ ue,
                       const float* __restrict__ ie,
                       const float* __restrict__ a_src,
                       const float* __restrict__ a_dst) {
    __shared__ float sW[64 * 64];
    __shared__ float sxT[64][68];
    int t = threadIdx.x;
#pragma unroll
    for (int i = 0; i < 8; i++)
        *(float4*)&sW[(t + 128 * i) * 4] = *(const float4*)&W[(t + 128 * i) * 4];
    int n0 = blockIdx.x * 64;
#pragma unroll
    for (int i = 0; i < 8; i++) {
        int f = t + 128 * i;
        int node = f >> 4;
        int col  = (f & 15) * 4;
        int n = n0 + node;
        float4 v = make_float4(0.f, 0.f, 0.f, 0.f);
        if (n < NN) {
            const float* row = FIRST
                ? (n < N_USERS ? ue + (size_t)n * 64
                               : ie + (size_t)(n - N_USERS) * 64)
                : g_x + (size_t)n * 64;
            v = *(const float4*)(row + col);
        }
        sxT[col + 0][node] = v.x; sxT[col + 1][node] = v.y;
        sxT[col + 2][node] = v.z; sxT[col + 3][node] = v.w;
    }
    __syncthreads();
    int ng = t >> 3;
    int cg = t & 7;
    float acc[4][8];
#pragma unroll
    for (int i = 0; i < 4; i++)
#pragma unroll
        for (int j = 0; j < 8; j++) acc[i][j] = 0.f;
#pragma unroll 4
    for (int k = 0; k < 64; k++) {
        float4 xv = *(float4*)&sxT[k][ng * 4];
        float4 w0 = *(float4*)&sW[k * 64 + cg * 8];
        float4 w1 = *(float4*)&sW[k * 64 + cg * 8 + 4];
        float xi;
#pragma unroll
        for (int i = 0; i < 4; i++) {
            xi = (i == 0) ? xv.x : (i == 1) ? xv.y : (i == 2) ? xv.z : xv.w;
            acc[i][0] += xi * w0.x; acc[i][1] += xi * w0.y;
            acc[i][2] += xi * w0.z; acc[i][3] += xi * w0.w;
            acc[i][4] += xi * w1.x; acc[i][5] += xi * w1.y;
            acc[i][6] += xi * w1.z; acc[i][7] += xi * w1.w;
        }
    }
#pragma unroll
    for (int i = 0; i < 4; i++) {
        int n = n0 + ng * 4 + i;
        if (n < NN) {
            __nv_bfloat162 b0 = __float22bfloat162_rn(make_float2(acc[i][0], acc[i][1]));
            __nv_bfloat162 b1 = __float22bfloat162_rn(make_float2(acc[i][2], acc[i][3]));
            __nv_bfloat162 b2 = __float22bfloat162_rn(make_float2(acc[i][4], acc[i][5]));
            __nv_bfloat162 b3 = __float22bfloat162_rn(make_float2(acc[i][6], acc[i][7]));
            uint4 pk;
            pk.x = *(unsigned*)&b0; pk.y = *(unsigned*)&b1;
            pk.z = *(unsigned*)&b2; pk.w = *(unsigned*)&b3;
            *(uint4*)&g_hb[(size_t)n * 64 + cg * 8] = pk;
        }
    }
    float4 av0 = *(const float4*)&a_src[cg * 8];
    float4 av1 = *(const float4*)&a_src[cg * 8 + 4];
    float4 dv0 = *(const float4*)&a_dst[cg * 8];
    float4 dv1 = *(const float4*)&a_dst[cg * 8 + 4];
    float ps[4], pd[4];
#pragma unroll
    for (int i = 0; i < 4; i++) {
        ps[i] = acc[i][0]*av0.x + acc[i][1]*av0.y + acc[i][2]*av0.z + acc[i][3]*av0.w
              + acc[i][4]*av1.x + acc[i][5]*av1.y + acc[i][6]*av1.z + acc[i][7]*av1.w;
        pd[i] = acc[i][0]*dv0.x + acc[i][1]*dv0.y + acc[i][2]*dv0.z + acc[i][3]*dv0.w
              + acc[i][4]*dv1.x + acc[i][5]*dv1.y + acc[i][6]*dv1.z + acc[i][7]*dv1.w;
    }
    if (H == 4) {
#pragma unroll
        for (int i = 0; i < 4; i++) {
            ps[i] += __shfl_xor_sync(0xffffffffu, ps[i], 1);
            pd[i] += __shfl_xor_sync(0xffffffffu, pd[i], 1);
        }
        if ((cg & 1) == 0) {
            int head = cg >> 1;
#pragma unroll
            for (int i = 0; i < 4; i++) {
                int n = n0 + ng * 4 + i;
                if (n < NN) {
                    g_as[n * 4 + head] = ps[i];
                    g_ad[n * 4 + head] = pd[i];
                }
            }
        }
    } else {
#pragma unroll
        for (int i = 0; i < 4; i++) {
            ps[i] += __shfl_xor_sync(0xffffffffu, ps[i], 1);
            ps[i] += __shfl_xor_sync(0xffffffffu, ps[i], 2);
            ps[i] += __shfl_xor_sync(0xffffffffu, ps[i], 4);
            pd[i] += __shfl_xor_sync(0xffffffffu, pd[i], 1);
            pd[i] += __shfl_xor_sync(0xffffffffu, pd[i], 2);
            pd[i] += __shfl_xor_sync(0xffffffffu, pd[i], 4);
        }
        if (cg == 0) {
#pragma unroll
            for (int i = 0; i < 4; i++) {
                int n = n0 + ng * 4 + i;
                if (n < NN) { g_as[n] = ps[i]; g_ad[n] = pd[i]; }
            }
        }
    }
}

// ---------------- fused aggregation: 4 nodes/warp + cp.async smem pipeline ---
// Round-7 shape (8 accs, 8 lanes/node, full 128B row per node gather), but the
// h-row gathers of batch k+1 are staged GMEM->SMEM via cp.async (no register
// cost) while batch k is consumed from SMEM. Weights prefetched in registers
// (+8 regs only). Batches padded to 4 (pad: own row, w=0) -> no tail path.
template <int H, int F>
__global__ void __launch_bounds__(256) k_agg(const float* __restrict__ b) {
    // [warp][stage][quad*4+q][l] : 8*2*16*8*16B = 32KB
    __shared__ uint4 sbuf[8][2][16][8];
    int lane = threadIdx.x & 31;
    int wrp  = threadIdx.x >> 5;
    int quad = lane >> 3;
    int l    = lane & 7;
    int n    = blockIdx.x * 32 + wrp * 4 + quad;
    if (n >= NN) return;
    int c0   = l * 8;
    int head = c0 / F;

    float ad_d = __ldg(&g_ad[(size_t)n * H + head]);
    float den  = __expf(lrelu(__ldg(&g_as[(size_t)n * H + head]) + ad_d));
    const char* hbase = (const char*)g_hb;         // row = 128B (64 bf16)
    uint4 hs = *(const uint4*)(hbase + (size_t)n * 128 + l * 16);
    float2 h01 = bf2f(hs.x), h23 = bf2f(hs.y), h45 = bf2f(hs.z), h67 = bf2f(hs.w);
    float a0 = den * h01.x, a1 = den * h01.y, a2 = den * h23.x, a3 = den * h23.y;
    float a4 = den * h45.x, a5 = den * h45.y, a6 = den * h67.x, a7 = den * h67.y;

    int beg = g_off[n], end = g_off[n + 1];
    int nb = (end - beg + 3) >> 2;                 // padded batches of 4

    float wc[4], wn[4];
    int stage = 0;

    auto prefetch = [&](int k, int st, float* w) {
        int base = beg + k * 4;
#pragma unroll
        for (int q = 0; q < 4; q++) {
            int idx = base + q;
            int s = n;
            float wq = 0.f;
            if (idx < end) {
                s = __ldg(&g_adj[idx]);
                wq = __expf(lrelu(__ldg(&g_as[(size_t)s * H + head]) + ad_d));
            }
            w[q] = wq;
            unsigned dst = (unsigned)__cvta_generic_to_shared(
                               &sbuf[wrp][st][quad * 4 + q][l]);
            const void* src = hbase + (size_t)s * 128 + l * 16;
            asm volatile("cp.async.ca.shared.global [%0], [%1], 16;\n"
                         :: "r"(dst), "l"(src) : "memory");
        }
        asm volatile("cp.async.commit_group;\n" ::: "memory");
    };

    if (nb > 0) prefetch(0, 0, wc);
    for (int k = 0; k < nb; k++) {
        bool more = (k + 1 < nb);
        if (more) {
            prefetch(k + 1, stage ^ 1, wn);
            asm volatile("cp.async.wait_group 1;\n" ::: "memory");
        } else {
            asm volatile("cp.async.wait_group 0;\n" ::: "memory");
        }
#pragma unroll
        for (int q = 0; q < 4; q++) {
            uint4 p = sbuf[wrp][stage][quad * 4 + q][l];
            float2 q01 = bf2f(p.x), q23 = bf2f(p.y);
            float2 q45 = bf2f(p.z), q67 = bf2f(p.w);
            float wq = wc[q];
            den += wq;
            a0 += wq * q01.x; a1 += wq * q01.y;
            a2 += wq * q23.x; a3 += wq * q23.y;
            a4 += wq * q45.x; a5 += wq * q45.y;
            a6 += wq * q67.x; a7 += wq * q67.y;
        }
        if (more) {
#pragma unroll
            for (int q = 0; q < 4; q++) wc[q] = wn[q];
        }
        stage ^= 1;
    }

    float inv = 1.f / den;
    float4 o0, o1;
    o0.x = eluf(a0 * inv + b[c0 + 0]);
    o0.y = eluf(a1 * inv + b[c0 + 1]);
    o0.z = eluf(a2 * inv + b[c0 + 2]);
    o0.w = eluf(a3 * inv + b[c0 + 3]);
    o1.x = eluf(a4 * inv + b[c0 + 4]);
    o1.y = eluf(a5 * inv + b[c0 + 5]);
    o1.z = eluf(a6 * inv + b[c0 + 6]);
    o1.w = eluf(a7 * inv + b[c0 + 7]);
    *(float4*)&g_x[(size_t)n * 64 + c0]     = o0;
    *(float4*)&g_x[(size_t)n * 64 + c0 + 4] = o1;
}

// ---------------- final scoring ----------------------------------------------
__global__ void k_score(const void* __restrict__ bu_, const void* __restrict__ bi_,
                        float* __restrict__ out) {
    int gid = blockIdx.x * blockDim.x + threadIdx.x;
    if (gid >= NB * 8) return;
    int p = gid >> 3, l = gid & 7;
    int u, it;
    if (g_is64) {
        u  = (int)((const long long*)bu_)[p];
        it = (int)((const long long*)bi_)[p];
    } else {
        u  = ((const int*)bu_)[p];
        it = ((const int*)bi_)[p];
    }
    const float* xu = &g_x[(long)u * 64];
    const float* xv = &g_x[((long)it + N_USERS) * 64];
    int o = l * 8;
    float acc = 0.f;
#pragma unroll
    for (int k = 0; k < 8; k++) acc += xu[o + k] * xv[o + k];
    acc += __shfl_xor_sync(0xffffffffu, acc, 1);
    acc += __shfl_xor_sync(0xffffffffu, acc, 2);
    acc += __shfl_xor_sync(0xffffffffu, acc, 4);
    if (l == 0) out[p] = 1.f / (1.f + expf(-acc));
}

// ---------------- host launcher ----------------------------------------------
extern "C" void kernel_launch(void* const* d_in, const int* in_sizes, int n_in,
                              void* d_out, int out_size) {
    const void *edge = nullptr, *bu = nullptr, *bi = nullptr;
    const float *ue = nullptr, *ie = nullptr, *W1 = nullptr, *W2 = nullptr;
    const float* v64[6] = {nullptr, nullptr, nullptr, nullptr, nullptr, nullptr};
    int c64 = 0;
    for (int i = 0; i < n_in; i++) {
        int sz = in_sizes[i];
        if      (sz == 2 * NE)        edge = d_in[i];
        else if (sz == NB)            { if (!bu) bu = d_in[i]; else bi = d_in[i]; }
        else if (sz == N_USERS * DD)  ue = (const float*)d_in[i];
        else if (sz == N_ITEMS * DD)  ie = (const float*)d_in[i];
        else if (sz == DD * DD)       { if (!W1) W1 = (const float*)d_in[i];
                                        else     W2 = (const float*)d_in[i]; }
        else if (sz == 64 && c64 < 6) v64[c64++] = (const float*)d_in[i];
    }
    const float *as1 = v64[0], *ad1 = v64[1], *b1 = v64[2];
    const float *as2 = v64[3], *ad2 = v64[4], *b2 = v64[5];

    const int TB = 256;
    const int EB = (NE + TB - 1) / TB;

    k_init   <<<(NN + TB - 1) / TB, TB>>>((const int*)edge);
    k_count  <<<EB, TB>>>(edge);
    k_s1     <<<SB, 256>>>();
    k_s2     <<<1, 1024>>>();
    k_s3     <<<SB, 256>>>();
    k_scatter<<<EB, TB>>>(edge);

    // ---- layer 1: H=4, F=16 ----
    k_gemm<true, 4> <<<(NN + 63) / 64, 128>>>(W1, ue, ie, as1, ad1);
    k_agg <4, 16>   <<<(NN + 31) / 32, TB>>>(b1);

    // ---- layer 2: H=1, F=64 ----
    k_gemm<false, 1><<<(NN + 63) / 64, 128>>>(W2, nullptr, nullptr, as2, ad2);
    k_agg <1, 64>   <<<(NN + 31) / 32, TB>>>(b2);

    k_score<<<(NB * 8 + TB - 1) / TB, TB>>>(bu, bi, (float*)d_out);
}

// round 13
// speedup vs baseline: 1.4565x; 1.4565x over previous
#include <cuda_runtime.h>
#include <cuda_bf16.h>

#define N_USERS 100000
#define N_ITEMS 50000
#define NN      150000
#define NE      2000000
#define DD      64
#define NB      16384
#define SB      586      // ceil(NN/256) scan blocks

// ---------------- scratch (device globals) ----------------------------------
__device__ __nv_bfloat16  g_xb[NN*DD];    // layer outputs (bf16)
__device__ __nv_bfloat16  g_hb[NN*DD];    // h = x@W in bf16 (gather payload)
__device__ float g_as [NN*4];
__device__ float g_ad [NN*4];
__device__ int   g_adj[NE];
__device__ int   g_cnt[NN];
__device__ int   g_off[NN+1];
__device__ int   g_pos[NN];
__device__ int   g_spine[1024];
__device__ int   g_is64;

// ---------------- helpers ---------------------------------------------------
__device__ __forceinline__ float lrelu(float x) { return x > 0.f ? x : 0.2f * x; }
__device__ __forceinline__ float eluf (float v) { return v > 0.f ? v : expf(v) - 1.f; }
__device__ __forceinline__ float2 bf2f(unsigned u) {
    return __bfloat1622float2(*(__nv_bfloat162*)&u);
}
__device__ __forceinline__ unsigned f2bf2(float a, float b) {
    __nv_bfloat162 p = __float22bfloat162_rn(make_float2(a, b));
    return *(unsigned*)&p;
}
__device__ __forceinline__ unsigned smaddr(const void* p) {
    return (unsigned)__cvta_generic_to_shared(p);
}
__device__ __forceinline__ void ldsm_x4(unsigned* r, unsigned a) {
    asm volatile("ldmatrix.sync.aligned.m8n8.x4.shared.b16 {%0,%1,%2,%3}, [%4];"
                 : "=r"(r[0]), "=r"(r[1]), "=r"(r[2]), "=r"(r[3]) : "r"(a));
}
__device__ __forceinline__ void ldsm_x2t(unsigned* r, unsigned a) {
    asm volatile("ldmatrix.sync.aligned.m8n8.x2.trans.shared.b16 {%0,%1}, [%2];"
                 : "=r"(r[0]), "=r"(r[1]) : "r"(a));
}
__device__ __forceinline__ void mma_bf16(float* c, const unsigned* a, const unsigned* b) {
    asm volatile("mma.sync.aligned.m16n8k16.row.col.f32.bf16.bf16.f32 "
                 "{%0,%1,%2,%3}, {%4,%5,%6,%7}, {%8,%9}, {%0,%1,%2,%3};"
                 : "+f"(c[0]), "+f"(c[1]), "+f"(c[2]), "+f"(c[3])
                 : "r"(a[0]), "r"(a[1]), "r"(a[2]), "r"(a[3]),
                   "r"(b[0]), "r"(b[1]));
}

// ---------------- init: zero counters + dtype detect -------------------------
__global__ void k_init(const int* __restrict__ ei) {
    int i = blockIdx.x * blockDim.x + threadIdx.x;
    if (i < NN) g_cnt[i] = 0;
    if (blockIdx.x == 0 && threadIdx.x == 0) {
        int all0 = 1;
        for (int k = 0; k < 64; k++)
            if (ei[2 * k + 1] != 0) { all0 = 0; break; }
        g_is64 = all0;
    }
}

__global__ void k_count(const void* __restrict__ ei) {
    int e = blockIdx.x * blockDim.x + threadIdx.x;
    if (e >= NE) return;
    int d = g_is64 ? (int)((const long long*)ei)[NE + e]
                   : ((const int*)ei)[NE + e];
    atomicAdd(&g_cnt[d], 1);
}

__global__ void k_s1() {
    __shared__ int ws[8];
    int t = threadIdx.x;
    int i = blockIdx.x * 256 + t;
    int v = (i < NN) ? g_cnt[i] : 0;
#pragma unroll
    for (int d = 16; d; d >>= 1) v += __shfl_xor_sync(0xffffffffu, v, d);
    if ((t & 31) == 0) ws[t >> 5] = v;
    __syncthreads();
    if (t < 8) {
        int s = ws[t];
#pragma unroll
        for (int d = 4; d; d >>= 1) s += __shfl_xor_sync(0xffu, s, d);
        if (t == 0) g_spine[blockIdx.x] = s;
    }
}

template <int NVALID>
__device__ __forceinline__ void scan1024(int* arr) {
    __shared__ int ws[32];
    int t = threadIdx.x;
    int orig = (t < NVALID) ? arr[t] : 0;
    int v = orig;
#pragma unroll
    for (int d = 1; d < 32; d <<= 1) {
        int u = __shfl_up_sync(0xffffffffu, v, d);
        if ((t & 31) >= d) v += u;
    }
    if ((t & 31) == 31) ws[t >> 5] = v;
    __syncthreads();
    if (t < 32) {
        int s = ws[t];
#pragma unroll
        for (int d = 1; d < 32; d <<= 1) {
            int u = __shfl_up_sync(0xffffffffu, s, d);
            if (t >= d) s += u;
        }
        ws[t] = s;
    }
    __syncthreads();
    int incl = v + ((t >= 32) ? ws[(t >> 5) - 1] : 0);
    if (t < NVALID) arr[t] = incl - orig;
}

__global__ void k_s2() {
    scan1024<SB>(g_spine);
    if (threadIdx.x == 0) g_off[NN] = NE;
}

__global__ void k_s3() {
    __shared__ int ws[8];
    int t = threadIdx.x;
    int i = blockIdx.x * 256 + t;
    int orig = (i < NN) ? g_cnt[i] : 0;
    int v = orig;
#pragma unroll
    for (int d = 1; d < 32; d <<= 1) {
        int u = __shfl_up_sync(0xffffffffu, v, d);
        if ((t & 31) >= d) v += u;
    }
    if ((t & 31) == 31) ws[t >> 5] = v;
    __syncthreads();
    if (t < 8) {
        int s = ws[t];
#pragma unroll
        for (int d = 1; d < 8; d <<= 1) {
            int u = __shfl_up_sync(0xffu, s, d);
            if (t >= d) s += u;
        }
        ws[t] = s;
    }
    __syncthreads();
    int incl = v + ((t >= 32) ? ws[(t >> 5) - 1] : 0);
    int excl = incl - orig + g_spine[blockIdx.x];
    if (i < NN) { g_off[i] = excl; g_pos[i] = excl; }
}

__global__ void k_scatter(const void* __restrict__ ei) {
    int e = blockIdx.x * blockDim.x + threadIdx.x;
    if (e >= NE) return;
    int s, d;
    if (g_is64) {
        const long long* p = (const long long*)ei;
        s = (int)p[e]; d = (int)p[NE + e];
    } else {
        const int* p = (const int*)ei;
        s = p[e]; d = p[NE + e];
    }
    int pos = atomicAdd(&g_pos[d], 1);
    g_adj[pos] = s;
}

// ---------------- tensor-core GEMM + fused alpha ------------------------------
// 256 threads (8 warps), 128 nodes/block. bf16 mma.sync m16n8k16, fp32 accum.
// Epilogue stages h (bf16) in smem, then writes g_hb + computes alpha dots.
template <bool FIRST, int H>
__global__ void __launch_bounds__(256) k_gemm(const float* __restrict__ W,
                       const float* __restrict__ ue,
                       const float* __restrict__ ie,
                       const float* __restrict__ a_src,
                       const float* __restrict__ a_dst) {
    __shared__ __nv_bfloat16 sW[64][72];   // W bf16, padded rows (144B)
    __shared__ __nv_bfloat16 sX[128][72];  // x bf16 / h staging
    int t = threadIdx.x;
    int n0 = blockIdx.x * 128;

    // load W (64x64 fp32 -> bf16): thread = row t>>2, 16 cols
    {
        int r = t >> 2, cg = (t & 3) * 16;
#pragma unroll
        for (int i = 0; i < 4; i++) {
            float4 v = *(const float4*)&W[r * 64 + cg + i * 4];
            *(unsigned*)&sW[r][cg + i * 4 + 0] = f2bf2(v.x, v.y);
            *(unsigned*)&sW[r][cg + i * 4 + 2] = f2bf2(v.z, v.w);
        }
    }
    // load X (128 rows): thread = row t>>1, 32 cols
    {
        int r = t >> 1, hf = (t & 1) * 32;
        int n = n0 + r;
        if (FIRST) {
            if (n < NN) {
                const float* row = (n < N_USERS) ? ue + (size_t)n * 64
                                                 : ie + (size_t)(n - N_USERS) * 64;
#pragma unroll
                for (int i = 0; i < 8; i++) {
                    float4 v = *(const float4*)&row[hf + i * 4];
                    *(unsigned*)&sX[r][hf + i * 4 + 0] = f2bf2(v.x, v.y);
                    *(unsigned*)&sX[r][hf + i * 4 + 2] = f2bf2(v.z, v.w);
                }
            } else {
#pragma unroll
                for (int i = 0; i < 16; i++) *(unsigned*)&sX[r][hf + i * 2] = 0u;
            }
        } else {
            if (n < NN) {
                const uint4* src = (const uint4*)&g_xb[(size_t)n * 64 + hf];
#pragma unroll
                for (int i = 0; i < 4; i++) *(uint4*)&sX[r][hf + i * 8] = src[i];
            } else {
#pragma unroll
                for (int i = 0; i < 16; i++) *(unsigned*)&sX[r][hf + i * 2] = 0u;
            }
        }
    }
    __syncthreads();

    int wid = t >> 5, lane = t & 31;
    int m0 = wid * 16;
    int grp = lane >> 3, li = lane & 7;

    // A fragments for all 4 k-chunks (warp-private rows m0..m0+15)
    unsigned afr[4][4];
    {
        int row = m0 + ((grp & 1) ? 8 : 0) + li;
#pragma unroll
        for (int kc = 0; kc < 4; kc++) {
            int col = kc * 16 + ((grp & 2) ? 8 : 0);
            ldsm_x4(afr[kc], smaddr(&sX[row][col]));
        }
    }
    // MMA: 8 n-tiles x 4 k-chunks
    float cfr[8][4];
#pragma unroll
    for (int nt = 0; nt < 8; nt++)
#pragma unroll
        for (int q = 0; q < 4; q++) cfr[nt][q] = 0.f;
    {
        int brow = lane & 15;
#pragma unroll
        for (int nt = 0; nt < 8; nt++) {
#pragma unroll
            for (int kc = 0; kc < 4; kc++) {
                unsigned bfr[2];
                ldsm_x2t(bfr, smaddr(&sW[kc * 16 + brow][nt * 8]));
                mma_bf16(cfr[nt], afr[kc], bfr);
            }
        }
    }
    // stage C -> sX (bf16), warp-private rows
    {
        int r = m0 + (lane >> 2);
        int cbase = (lane & 3) * 2;
#pragma unroll
        for (int nt = 0; nt < 8; nt++) {
            int c = nt * 8 + cbase;
            *(unsigned*)&sX[r][c]     = f2bf2(cfr[nt][0], cfr[nt][1]);
            *(unsigned*)&sX[r + 8][c] = f2bf2(cfr[nt][2], cfr[nt][3]);
        }
    }
    __syncthreads();

    // final epilogue: thread = (node t>>1, half t&1): write g_hb + alpha
    {
        int nb = t >> 1, hf = (t & 1) * 32;
        int n = n0 + nb;
        uint4 v0 = *(const uint4*)&sX[nb][hf];
        uint4 v1 = *(const uint4*)&sX[nb][hf + 8];
        uint4 v2 = *(const uint4*)&sX[nb][hf + 16];
        uint4 v3 = *(const uint4*)&sX[nb][hf + 24];
        if (n < NN) {
            uint4* dst = (uint4*)&g_hb[(size_t)n * 64 + hf];
            dst[0] = v0; dst[1] = v1; dst[2] = v2; dst[3] = v3;
        }
        unsigned hw[16] = { v0.x, v0.y, v0.z, v0.w, v1.x, v1.y, v1.z, v1.w,
                            v2.x, v2.y, v2.z, v2.w, v3.x, v3.y, v3.z, v3.w };
        if (H == 4) {
            // two heads per half: head hf/16 and hf/16+1 (16 cols each)
            float ps0 = 0.f, pd0 = 0.f, ps1 = 0.f, pd1 = 0.f;
#pragma unroll
            for (int i = 0; i < 8; i++) {
                float2 hv = bf2f(hw[i]);
                int c = hf + i * 2;
                ps0 += hv.x * a_src[c] + hv.y * a_src[c + 1];
                pd0 += hv.x * a_dst[c] + hv.y * a_dst[c + 1];
            }
#pragma unroll
            for (int i = 8; i < 16; i++) {
                float2 hv = bf2f(hw[i]);
                int c = hf + i * 2;
                ps1 += hv.x * a_src[c] + hv.y * a_src[c + 1];
                pd1 += hv.x * a_dst[c] + hv.y * a_dst[c + 1];
            }
            if (n < NN) {
                int h0 = hf / 16;
                g_as[n * 4 + h0]     = ps0;
                g_ad[n * 4 + h0]     = pd0;
                g_as[n * 4 + h0 + 1] = ps1;
                g_ad[n * 4 + h0 + 1] = pd1;
            }
        } else {
            float ps = 0.f, pd = 0.f;
#pragma unroll
            for (int i = 0; i < 16; i++) {
                float2 hv = bf2f(hw[i]);
                int c = hf + i * 2;
                ps += hv.x * a_src[c] + hv.y * a_src[c + 1];
                pd += hv.x * a_dst[c] + hv.y * a_dst[c + 1];
            }
            ps += __shfl_xor_sync(0xffffffffu, ps, 1);
            pd += __shfl_xor_sync(0xffffffffu, pd, 1);
            if (n < NN && (t & 1) == 0) { g_as[n] = ps; g_ad[n] = pd; }
        }
    }
}

// ---------------- fused aggregation (round-7 shape, bf16 output) -------------
// 4 nodes/warp, 8 lanes/node, lane owns 8 cols (uint4 = full 128B row gather).
template <int H, int F>
__global__ void k_agg(const float* __restrict__ b) {
    int lane = threadIdx.x & 31;
    int wrp  = threadIdx.x >> 5;
    int quad = lane >> 3;
    int l    = lane & 7;
    int n    = blockIdx.x * 32 + wrp * 4 + quad;
    if (n >= NN) return;
    int c0   = l * 8;
    int head = c0 / F;

    float ad_d = __ldg(&g_ad[(size_t)n * H + head]);
    float den  = __expf(lrelu(__ldg(&g_as[(size_t)n * H + head]) + ad_d));
    const uint4* hb = (const uint4*)g_hb;          // row = 8 uint4 (64 bf16)
    uint4 hs = hb[(size_t)n * 8 + l];
    float2 h01 = bf2f(hs.x), h23 = bf2f(hs.y), h45 = bf2f(hs.z), h67 = bf2f(hs.w);
    float a0 = den * h01.x, a1 = den * h01.y, a2 = den * h23.x, a3 = den * h23.y;
    float a4 = den * h45.x, a5 = den * h45.y, a6 = den * h67.x, a7 = den * h67.y;

    int beg = g_off[n], end = g_off[n + 1];
    int j = beg;
    for (; j + 4 <= end; j += 4) {
        int s[4]; float w[4]; uint4 p[4];
#pragma unroll
        for (int q = 0; q < 4; q++) s[q] = __ldg(&g_adj[j + q]);
#pragma unroll
        for (int q = 0; q < 4; q++)
            w[q] = __expf(lrelu(__ldg(&g_as[(size_t)s[q] * H + head]) + ad_d));
#pragma unroll
        for (int q = 0; q < 4; q++) p[q] = hb[(size_t)s[q] * 8 + l];
#pragma unroll
        for (int q = 0; q < 4; q++) {
            float2 q01 = bf2f(p[q].x), q23 = bf2f(p[q].y);
            float2 q45 = bf2f(p[q].z), q67 = bf2f(p[q].w);
            den += w[q];
            a0 += w[q] * q01.x; a1 += w[q] * q01.y;
            a2 += w[q] * q23.x; a3 += w[q] * q23.y;
            a4 += w[q] * q45.x; a5 += w[q] * q45.y;
            a6 += w[q] * q67.x; a7 += w[q] * q67.y;
        }
    }
    for (; j < end; j++) {
        int s = __ldg(&g_adj[j]);
        float w = __expf(lrelu(__ldg(&g_as[(size_t)s * H + head]) + ad_d));
        uint4 p = hb[(size_t)s * 8 + l];
        float2 q01 = bf2f(p.x), q23 = bf2f(p.y), q45 = bf2f(p.z), q67 = bf2f(p.w);
        den += w;
        a0 += w * q01.x; a1 += w * q01.y; a2 += w * q23.x; a3 += w * q23.y;
        a4 += w * q45.x; a5 += w * q45.y; a6 += w * q67.x; a7 += w * q67.y;
    }
    float inv = 1.f / den;
    uint4 o;
    o.x = f2bf2(eluf(a0 * inv + b[c0 + 0]), eluf(a1 * inv + b[c0 + 1]));
    o.y = f2bf2(eluf(a2 * inv + b[c0 + 2]), eluf(a3 * inv + b[c0 + 3]));
    o.z = f2bf2(eluf(a4 * inv + b[c0 + 4]), eluf(a5 * inv + b[c0 + 5]));
    o.w = f2bf2(eluf(a6 * inv + b[c0 + 6]), eluf(a7 * inv + b[c0 + 7]));
    *(uint4*)&g_xb[(size_t)n * 64 + c0] = o;
}

// ---------------- final scoring (bf16 features) -------------------------------
__global__ void k_score(const void* __restrict__ bu_, const void* __restrict__ bi_,
                        float* __restrict__ out) {
    int gid = blockIdx.x * blockDim.x + threadIdx.x;
    if (gid >= NB * 8) return;
    int p = gid >> 3, l = gid & 7;
    int u, it;
    if (g_is64) {
        u  = (int)((const long long*)bu_)[p];
        it = (int)((const long long*)bi_)[p];
    } else {
        u  = ((const int*)bu_)[p];
        it = ((const int*)bi_)[p];
    }
    const uint4* xb = (const uint4*)g_xb;
    uint4 av = xb[(size_t)u * 8 + l];
    uint4 bv = xb[((size_t)it + N_USERS) * 8 + l];
    float acc = 0.f;
    {
        float2 a01 = bf2f(av.x), b01 = bf2f(bv.x);
        float2 a23 = bf2f(av.y), b23 = bf2f(bv.y);
        float2 a45 = bf2f(av.z), b45 = bf2f(bv.z);
        float2 a67 = bf2f(av.w), b67 = bf2f(bv.w);
        acc = a01.x * b01.x + a01.y * b01.y + a23.x * b23.x + a23.y * b23.y
            + a45.x * b45.x + a45.y * b45.y + a67.x * b67.x + a67.y * b67.y;
    }
    acc += __shfl_xor_sync(0xffffffffu, acc, 1);
    acc += __shfl_xor_sync(0xffffffffu, acc, 2);
    acc += __shfl_xor_sync(0xffffffffu, acc, 4);
    if (l == 0) out[p] = 1.f / (1.f + expf(-acc));
}

// ---------------- host launcher ----------------------------------------------
extern "C" void kernel_launch(void* const* d_in, const int* in_sizes, int n_in,
                              void* d_out, int out_size) {
    const void *edge = nullptr, *bu = nullptr, *bi = nullptr;
    const float *ue = nullptr, *ie = nullptr, *W1 = nullptr, *W2 = nullptr;
    const float* v64[6] = {nullptr, nullptr, nullptr, nullptr, nullptr, nullptr};
    int c64 = 0;
    for (int i = 0; i < n_in; i++) {
        int sz = in_sizes[i];
        if      (sz == 2 * NE)        edge = d_in[i];
        else if (sz == NB)            { if (!bu) bu = d_in[i]; else bi = d_in[i]; }
        else if (sz == N_USERS * DD)  ue = (const float*)d_in[i];
        else if (sz == N_ITEMS * DD)  ie = (const float*)d_in[i];
        else if (sz == DD * DD)       { if (!W1) W1 = (const float*)d_in[i];
                                        else     W2 = (const float*)d_in[i]; }
        else if (sz == 64 && c64 < 6) v64[c64++] = (const float*)d_in[i];
    }
    const float *as1 = v64[0], *ad1 = v64[1], *b1 = v64[2];
    const float *as2 = v64[3], *ad2 = v64[4], *b2 = v64[5];

    const int TB = 256;
    const int EB = (NE + TB - 1) / TB;

    k_init   <<<(NN + TB - 1) / TB, TB>>>((const int*)edge);
    k_count  <<<EB, TB>>>(edge);
    k_s1     <<<SB, 256>>>();
    k_s2     <<<1, 1024>>>();
    k_s3     <<<SB, 256>>>();
    k_scatter<<<EB, TB>>>(edge);

    // ---- layer 1: H=4, F=16 ----
    k_gemm<true, 4> <<<(NN + 127) / 128, 256>>>(W1, ue, ie, as1, ad1);
    k_agg <4, 16>   <<<(NN + 31) / 32, TB>>>(b1);

    // ---- layer 2: H=1, F=64 ----
    k_gemm<false, 1><<<(NN + 127) / 128, 256>>>(W2, nullptr, nullptr, as2, ad2);
    k_agg <1, 64>   <<<(NN + 31) / 32, TB>>>(b2);

    k_score<<<(NB * 8 + TB - 1) / TB, TB>>>(bu, bi, (float*)d_out);
}

// round 14
// speedup vs baseline: 1.4924x; 1.0246x over previous
#include <cuda_runtime.h>
#include <cuda_bf16.h>

#define N_USERS 100000
#define N_ITEMS 50000
#define NN      150000
#define NE      2000000
#define DD      64
#define NB      16384
#define SB      586      // ceil(NN/256) scan blocks

// ---------------- scratch (device globals) ----------------------------------
__device__ __nv_bfloat16  g_xb[NN*DD];    // layer outputs (bf16)
__device__ __nv_bfloat16  g_hb[NN*DD];    // h = x@W in bf16 (gather payload)
__device__ float g_as [NN*4];
__device__ float g_ad [NN*4];
__device__ int   g_adj[NE];
__device__ int   g_cnt[NN];               // zero at entry (re-zeroed in k_s3)
__device__ int   g_off[NN+1];
__device__ int   g_pos[NN];
__device__ int   g_spine[1024];
__device__ int   g_is64;

// ---------------- helpers ---------------------------------------------------
__device__ __forceinline__ float lrelu(float x) { return x > 0.f ? x : 0.2f * x; }
__device__ __forceinline__ float eluf (float v) { return v > 0.f ? v : expf(v) - 1.f; }
__device__ __forceinline__ float2 bf2f(unsigned u) {
    return __bfloat1622float2(*(__nv_bfloat162*)&u);
}
__device__ __forceinline__ unsigned f2bf2(float a, float b) {
    __nv_bfloat162 p = __float22bfloat162_rn(make_float2(a, b));
    return *(unsigned*)&p;
}
__device__ __forceinline__ unsigned smaddr(const void* p) {
    return (unsigned)__cvta_generic_to_shared(p);
}
__device__ __forceinline__ void ldsm_x4(unsigned* r, unsigned a) {
    asm volatile("ldmatrix.sync.aligned.m8n8.x4.shared.b16 {%0,%1,%2,%3}, [%4];"
                 : "=r"(r[0]), "=r"(r[1]), "=r"(r[2]), "=r"(r[3]) : "r"(a));
}
__device__ __forceinline__ void ldsm_x2t(unsigned* r, unsigned a) {
    asm volatile("ldmatrix.sync.aligned.m8n8.x2.trans.shared.b16 {%0,%1}, [%2];"
                 : "=r"(r[0]), "=r"(r[1]) : "r"(a));
}
__device__ __forceinline__ void mma_bf16(float* c, const unsigned* a, const unsigned* b) {
    asm volatile("mma.sync.aligned.m16n8k16.row.col.f32.bf16.bf16.f32 "
                 "{%0,%1,%2,%3}, {%4,%5,%6,%7}, {%8,%9}, {%0,%1,%2,%3};"
                 : "+f"(c[0]), "+f"(c[1]), "+f"(c[2]), "+f"(c[3])
                 : "r"(a[0]), "r"(a[1]), "r"(a[2]), "r"(a[3]),
                   "r"(b[0]), "r"(b[1]));
}

// ---------------- detect dtype (1 warp) ---------------------------------------
__global__ void k_detect(const int* __restrict__ ei) {
    if (threadIdx.x == 0) {
        int all0 = 1;
        for (int k = 0; k < 64; k++)
            if (ei[2 * k + 1] != 0) { all0 = 0; break; }
        g_is64 = all0;
    }
}

__global__ void k_count(const void* __restrict__ ei) {
    int e = blockIdx.x * blockDim.x + threadIdx.x;
    if (e >= NE) return;
    int d = g_is64 ? (int)((const long long*)ei)[NE + e]
                   : ((const int*)ei)[NE + e];
    atomicAdd(&g_cnt[d], 1);
}

// block sums -> spine (shuffle reduce)
__global__ void k_s1() {
    __shared__ int ws[8];
    int t = threadIdx.x;
    int i = blockIdx.x * 256 + t;
    int v = (i < NN) ? g_cnt[i] : 0;
#pragma unroll
    for (int d = 16; d; d >>= 1) v += __shfl_xor_sync(0xffffffffu, v, d);
    if ((t & 31) == 0) ws[t >> 5] = v;
    __syncthreads();
    if (t < 8) {
        int s = ws[t];
#pragma unroll
        for (int d = 4; d; d >>= 1) s += __shfl_xor_sync(0xffu, s, d);
        if (t == 0) g_spine[blockIdx.x] = s;
    }
}

// per-block: spine prefix (computed locally) + intra-block scan + re-zero cnt
__global__ void k_s3() {
    __shared__ int ws[8];
    __shared__ int sbase;
    int t = threadIdx.x;
    int b = blockIdx.x;
    // exclusive prefix of spine[0..b)
    int acc = 0;
    for (int j = t; j < b; j += 256) acc += g_spine[j];
#pragma unroll
    for (int d = 16; d; d >>= 1) acc += __shfl_xor_sync(0xffffffffu, acc, d);
    if ((t & 31) == 0) ws[t >> 5] = acc;
    __syncthreads();
    if (t < 8) {
        int s = ws[t];
#pragma unroll
        for (int d = 4; d; d >>= 1) s += __shfl_xor_sync(0xffu, s, d);
        if (t == 0) sbase = s;
    }
    __syncthreads();
    // intra-block exclusive scan of cnt
    int i = b * 256 + t;
    int orig = (i < NN) ? g_cnt[i] : 0;
    int v = orig;
#pragma unroll
    for (int d = 1; d < 32; d <<= 1) {
        int u = __shfl_up_sync(0xffffffffu, v, d);
        if ((t & 31) >= d) v += u;
    }
    if ((t & 31) == 31) ws[t >> 5] = v;
    __syncthreads();
    if (t < 8) {
        int s = ws[t];
#pragma unroll
        for (int d = 1; d < 8; d <<= 1) {
            int u = __shfl_up_sync(0xffu, s, d);
            if (t >= d) s += u;
        }
        ws[t] = s;
    }
    __syncthreads();
    int incl = v + ((t >= 32) ? ws[(t >> 5) - 1] : 0);
    int excl = incl - orig + sbase;
    if (i < NN) { g_off[i] = excl; g_pos[i] = excl; g_cnt[i] = 0; }
    if (b == SB - 1 && t == 255) g_off[NN] = NE;
}

__global__ void k_scatter(const void* __restrict__ ei) {
    int e = blockIdx.x * blockDim.x + threadIdx.x;
    if (e >= NE) return;
    int s, d;
    if (g_is64) {
        const long long* p = (const long long*)ei;
        s = (int)p[e]; d = (int)p[NE + e];
    } else {
        const int* p = (const int*)ei;
        s = p[e]; d = p[NE + e];
    }
    int pos = atomicAdd(&g_pos[d], 1);
    g_adj[pos] = s;
}

// ---------------- tensor-core GEMM + fused alpha ------------------------------
// 256 threads (8 warps), 128 nodes/block. bf16 mma.sync m16n8k16, fp32 accum.
template <bool FIRST, int H>
__global__ void __launch_bounds__(256) k_gemm(const float* __restrict__ W,
                       const float* __restrict__ ue,
                       const float* __restrict__ ie,
                       const float* __restrict__ a_src,
                       const float* __restrict__ a_dst) {
    __shared__ __nv_bfloat16 sW[64][72];   // W bf16, padded rows
    __shared__ __nv_bfloat16 sX[128][72];  // x bf16 / h staging
    int t = threadIdx.x;
    int n0 = blockIdx.x * 128;

    {
        int r = t >> 2, cg = (t & 3) * 16;
#pragma unroll
        for (int i = 0; i < 4; i++) {
            float4 v = *(const float4*)&W[r * 64 + cg + i * 4];
            *(unsigned*)&sW[r][cg + i * 4 + 0] = f2bf2(v.x, v.y);
            *(unsigned*)&sW[r][cg + i * 4 + 2] = f2bf2(v.z, v.w);
        }
    }
    {
        int r = t >> 1, hf = (t & 1) * 32;
        int n = n0 + r;
        if (FIRST) {
            if (n < NN) {
                const float* row = (n < N_USERS) ? ue + (size_t)n * 64
                                                 : ie + (size_t)(n - N_USERS) * 64;
#pragma unroll
                for (int i = 0; i < 8; i++) {
                    float4 v = *(const float4*)&row[hf + i * 4];
                    *(unsigned*)&sX[r][hf + i * 4 + 0] = f2bf2(v.x, v.y);
                    *(unsigned*)&sX[r][hf + i * 4 + 2] = f2bf2(v.z, v.w);
                }
            } else {
#pragma unroll
                for (int i = 0; i < 16; i++) *(unsigned*)&sX[r][hf + i * 2] = 0u;
            }
        } else {
            if (n < NN) {
                const uint4* src = (const uint4*)&g_xb[(size_t)n * 64 + hf];
#pragma unroll
                for (int i = 0; i < 4; i++) *(uint4*)&sX[r][hf + i * 8] = src[i];
            } else {
#pragma unroll
                for (int i = 0; i < 16; i++) *(unsigned*)&sX[r][hf + i * 2] = 0u;
            }
        }
    }
    __syncthreads();

    int wid = t >> 5, lane = t & 31;
    int m0 = wid * 16;
    int grp = lane >> 3, li = lane & 7;

    unsigned afr[4][4];
    {
        int row = m0 + ((grp & 1) ? 8 : 0) + li;
#pragma unroll
        for (int kc = 0; kc < 4; kc++) {
            int col = kc * 16 + ((grp & 2) ? 8 : 0);
            ldsm_x4(afr[kc], smaddr(&sX[row][col]));
        }
    }
    float cfr[8][4];
#pragma unroll
    for (int nt = 0; nt < 8; nt++)
#pragma unroll
        for (int q = 0; q < 4; q++) cfr[nt][q] = 0.f;
    {
        int brow = lane & 15;
#pragma unroll
        for (int nt = 0; nt < 8; nt++) {
#pragma unroll
            for (int kc = 0; kc < 4; kc++) {
                unsigned bfr[2];
                ldsm_x2t(bfr, smaddr(&sW[kc * 16 + brow][nt * 8]));
                mma_bf16(cfr[nt], afr[kc], bfr);
            }
        }
    }
    {
        int r = m0 + (lane >> 2);
        int cbase = (lane & 3) * 2;
#pragma unroll
        for (int nt = 0; nt < 8; nt++) {
            int c = nt * 8 + cbase;
            *(unsigned*)&sX[r][c]     = f2bf2(cfr[nt][0], cfr[nt][1]);
            *(unsigned*)&sX[r + 8][c] = f2bf2(cfr[nt][2], cfr[nt][3]);
        }
    }
    __syncthreads();

    {
        int nb = t >> 1, hf = (t & 1) * 32;
        int n = n0 + nb;
        uint4 v0 = *(const uint4*)&sX[nb][hf];
        uint4 v1 = *(const uint4*)&sX[nb][hf + 8];
        uint4 v2 = *(const uint4*)&sX[nb][hf + 16];
        uint4 v3 = *(const uint4*)&sX[nb][hf + 24];
        if (n < NN) {
            uint4* dst = (uint4*)&g_hb[(size_t)n * 64 + hf];
            dst[0] = v0; dst[1] = v1; dst[2] = v2; dst[3] = v3;
        }
        unsigned hw[16] = { v0.x, v0.y, v0.z, v0.w, v1.x, v1.y, v1.z, v1.w,
                            v2.x, v2.y, v2.z, v2.w, v3.x, v3.y, v3.z, v3.w };
        if (H == 4) {
            float ps0 = 0.f, pd0 = 0.f, ps1 = 0.f, pd1 = 0.f;
#pragma unroll
            for (int i = 0; i < 8; i++) {
                float2 hv = bf2f(hw[i]);
                int c = hf + i * 2;
                ps0 += hv.x * a_src[c] + hv.y * a_src[c + 1];
                pd0 += hv.x * a_dst[c] + hv.y * a_dst[c + 1];
            }
#pragma unroll
            for (int i = 8; i < 16; i++) {
                float2 hv = bf2f(hw[i]);
                int c = hf + i * 2;
                ps1 += hv.x * a_src[c] + hv.y * a_src[c + 1];
                pd1 += hv.x * a_dst[c] + hv.y * a_dst[c + 1];
            }
            if (n < NN) {
                int h0 = hf / 16;
                g_as[n * 4 + h0]     = ps0;
                g_ad[n * 4 + h0]     = pd0;
                g_as[n * 4 + h0 + 1] = ps1;
                g_ad[n * 4 + h0 + 1] = pd1;
            }
        } else {
            float ps = 0.f, pd = 0.f;
#pragma unroll
            for (int i = 0; i < 16; i++) {
                float2 hv = bf2f(hw[i]);
                int c = hf + i * 2;
                ps += hv.x * a_src[c] + hv.y * a_src[c + 1];
                pd += hv.x * a_dst[c] + hv.y * a_dst[c + 1];
            }
            ps += __shfl_xor_sync(0xffffffffu, ps, 1);
            pd += __shfl_xor_sync(0xffffffffu, pd, 1);
            if (n < NN && (t & 1) == 0) { g_as[n] = ps; g_ad[n] = pd; }
        }
    }
}

// ---------------- fused aggregation (round-7 shape, bf16 output) -------------
template <int H, int F>
__global__ void k_agg(const float* __restrict__ b) {
    int lane = threadIdx.x & 31;
    int wrp  = threadIdx.x >> 5;
    int quad = lane >> 3;
    int l    = lane & 7;
    int n    = blockIdx.x * 32 + wrp * 4 + quad;
    if (n >= NN) return;
    int c0   = l * 8;
    int head = c0 / F;

    float ad_d = __ldg(&g_ad[(size_t)n * H + head]);
    float den  = __expf(lrelu(__ldg(&g_as[(size_t)n * H + head]) + ad_d));
    const uint4* hb = (const uint4*)g_hb;
    uint4 hs = hb[(size_t)n * 8 + l];
    float2 h01 = bf2f(hs.x), h23 = bf2f(hs.y), h45 = bf2f(hs.z), h67 = bf2f(hs.w);
    float a0 = den * h01.x, a1 = den * h01.y, a2 = den * h23.x, a3 = den * h23.y;
    float a4 = den * h45.x, a5 = den * h45.y, a6 = den * h67.x, a7 = den * h67.y;

    int beg = g_off[n], end = g_off[n + 1];
    int j = beg;
    for (; j + 4 <= end; j += 4) {
        int s[4]; float w[4]; uint4 p[4];
#pragma unroll
        for (int q = 0; q < 4; q++) s[q] = __ldg(&g_adj[j + q]);
#pragma unroll
        for (int q = 0; q < 4; q++)
            w[q] = __expf(lrelu(__ldg(&g_as[(size_t)s[q] * H + head]) + ad_d));
#pragma unroll
        for (int q = 0; q < 4; q++) p[q] = hb[(size_t)s[q] * 8 + l];
#pragma unroll
        for (int q = 0; q < 4; q++) {
            float2 q01 = bf2f(p[q].x), q23 = bf2f(p[q].y);
            float2 q45 = bf2f(p[q].z), q67 = bf2f(p[q].w);
            den += w[q];
            a0 += w[q] * q01.x; a1 += w[q] * q01.y;
            a2 += w[q] * q23.x; a3 += w[q] * q23.y;
            a4 += w[q] * q45.x; a5 += w[q] * q45.y;
            a6 += w[q] * q67.x; a7 += w[q] * q67.y;
        }
    }
    for (; j < end; j++) {
        int s = __ldg(&g_adj[j]);
        float w = __expf(lrelu(__ldg(&g_as[(size_t)s * H + head]) + ad_d));
        uint4 p = hb[(size_t)s * 8 + l];
        float2 q01 = bf2f(p.x), q23 = bf2f(p.y), q45 = bf2f(p.z), q67 = bf2f(p.w);
        den += w;
        a0 += w * q01.x; a1 += w * q01.y; a2 += w * q23.x; a3 += w * q23.y;
        a4 += w * q45.x; a5 += w * q45.y; a6 += w * q67.x; a7 += w * q67.y;
    }
    float inv = 1.f / den;
    uint4 o;
    o.x = f2bf2(eluf(a0 * inv + b[c0 + 0]), eluf(a1 * inv + b[c0 + 1]));
    o.y = f2bf2(eluf(a2 * inv + b[c0 + 2]), eluf(a3 * inv + b[c0 + 3]));
    o.z = f2bf2(eluf(a4 * inv + b[c0 + 4]), eluf(a5 * inv + b[c0 + 5]));
    o.w = f2bf2(eluf(a6 * inv + b[c0 + 6]), eluf(a7 * inv + b[c0 + 7]));
    *(uint4*)&g_xb[(size_t)n * 64 + c0] = o;
}

// ---------------- final scoring (bf16 features) -------------------------------
__global__ void k_score(const void* __restrict__ bu_, const void* __restrict__ bi_,
                        float* __restrict__ out) {
    int gid = blockIdx.x * blockDim.x + threadIdx.x;
    if (gid >= NB * 8) return;
    int p = gid >> 3, l = gid & 7;
    int u, it;
    if (g_is64) {
        u  = (int)((const long long*)bu_)[p];
        it = (int)((const long long*)bi_)[p];
    } else {
        u  = ((const int*)bu_)[p];
        it = ((const int*)bi_)[p];
    }
    const uint4* xb = (const uint4*)g_xb;
    uint4 av = xb[(size_t)u * 8 + l];
    uint4 bv = xb[((size_t)it + N_USERS) * 8 + l];
    float acc;
    {
        float2 a01 = bf2f(av.x), b01 = bf2f(bv.x);
        float2 a23 = bf2f(av.y), b23 = bf2f(bv.y);
        float2 a45 = bf2f(av.z), b45 = bf2f(bv.z);
        float2 a67 = bf2f(av.w), b67 = bf2f(bv.w);
        acc = a01.x * b01.x + a01.y * b01.y + a23.x * b23.x + a23.y * b23.y
            + a45.x * b45.x + a45.y * b45.y + a67.x * b67.x + a67.y * b67.y;
    }
    acc += __shfl_xor_sync(0xffffffffu, acc, 1);
    acc += __shfl_xor_sync(0xffffffffu, acc, 2);
    acc += __shfl_xor_sync(0xffffffffu, acc, 4);
    if (l == 0) out[p] = 1.f / (1.f + expf(-acc));
}

// ---------------- host launcher ----------------------------------------------
extern "C" void kernel_launch(void* const* d_in, const int* in_sizes, int n_in,
                              void* d_out, int out_size) {
    const void *edge = nullptr, *bu = nullptr, *bi = nullptr;
    const float *ue = nullptr, *ie = nullptr, *W1 = nullptr, *W2 = nullptr;
    const float* v64[6] = {nullptr, nullptr, nullptr, nullptr, nullptr, nullptr};
    int c64 = 0;
    for (int i = 0; i < n_in; i++) {
        int sz = in_sizes[i];
        if      (sz == 2 * NE)        edge = d_in[i];
        else if (sz == NB)            { if (!bu) bu = d_in[i]; else bi = d_in[i]; }
        else if (sz == N_USERS * DD)  ue = (const float*)d_in[i];
        else if (sz == N_ITEMS * DD)  ie = (const float*)d_in[i];
        else if (sz == DD * DD)       { if (!W1) W1 = (const float*)d_in[i];
                                        else     W2 = (const float*)d_in[i]; }
        else if (sz == 64 && c64 < 6) v64[c64++] = (const float*)d_in[i];
    }
    const float *as1 = v64[0], *ad1 = v64[1], *b1 = v64[2];
    const float *as2 = v64[3], *ad2 = v64[4], *b2 = v64[5];

    const int TB = 256;
    const int EB = (NE + TB - 1) / TB;
    const int GB = (NN + 127) / 128;

    // secondary stream + events for overlapping gemm1 with the CSR build.
    // Created once (host resources only; identical GPU work every call).
    static cudaStream_t s2 = nullptr;
    static cudaEvent_t  evA = nullptr, evB = nullptr;
    static int init_done = 0;
    if (!init_done) {
        if (cudaStreamCreateWithFlags(&s2, cudaStreamNonBlocking) != cudaSuccess) s2 = nullptr;
        if (cudaEventCreateWithFlags(&evA, cudaEventDisableTiming) != cudaSuccess) evA = nullptr;
        if (cudaEventCreateWithFlags(&evB, cudaEventDisableTiming) != cudaSuccess) evB = nullptr;
        init_done = 1;
    }

    bool fork = false;
    if (s2 && evA && evB) {
        if (cudaEventRecord(evA, 0) == cudaSuccess &&
            cudaStreamWaitEvent(s2, evA, 0) == cudaSuccess)
            fork = true;
    }

    if (fork) {
        k_gemm<true, 4><<<GB, 256, 0, s2>>>(W1, ue, ie, as1, ad1);
        if (cudaEventRecord(evB, s2) != cudaSuccess) fork = false; // fallback below re-launches
    }

    // CSR build chain (stream 0)
    k_detect <<<1, 32>>>((const int*)edge);
    k_count  <<<EB, TB>>>(edge);
    k_s1     <<<SB, 256>>>();
    k_s3     <<<SB, 256>>>();
    k_scatter<<<EB, TB>>>(edge);

    if (fork) {
        cudaStreamWaitEvent(0, evB, 0);   // join: gemm1 done before agg1
    } else {
        k_gemm<true, 4><<<GB, 256>>>(W1, ue, ie, as1, ad1);
    }

    // ---- layer 1 aggregation, layer 2, score (stream 0) ----
    k_agg <4, 16>   <<<(NN + 31) / 32, TB>>>(b1);
    k_gemm<false, 1><<<GB, 256>>>(W2, nullptr, nullptr, as2, ad2);
    k_agg <1, 64>   <<<(NN + 31) / 32, TB>>>(b2);
    k_score<<<(NB * 8 + TB - 1) / TB, TB>>>(bu, bi, (float*)d_out);
}